// round 10
// baseline (speedup 1.0000x reference)
#include <cuda_runtime.h>

#define NCH 27
#define HH 64
#define WW 64
#define OC 32
#define NB 2
#define PITCH 68   // tile row pitch (floats); 64 data + halo + pad, keeps 2p offsets 8B-aligned

typedef unsigned long long ull;

__device__ __forceinline__ ull addp(ull a, ull b) {
    ull r; asm("add.rn.f32x2 %0, %1, %2;" : "=l"(r) : "l"(a), "l"(b)); return r;
}
__device__ __forceinline__ ull mulp(ull a, ull b) {
    ull r; asm("mul.rn.f32x2 %0, %1, %2;" : "=l"(r) : "l"(a), "l"(b)); return r;
}
__device__ __forceinline__ ull fmap(ull a, ull b, ull c) {
    ull r; asm("fma.rn.f32x2 %0, %1, %2, %3;" : "=l"(r) : "l"(a), "l"(b), "l"(c)); return r;
}
__device__ __forceinline__ ull pack2(float lo, float hi) {
    ull r;
    asm("mov.b64 %0, {%1, %2};"
        : "=l"(r) : "r"(__float_as_uint(lo)), "r"(__float_as_uint(hi)));
    return r;
}

// packed maj3 on both lanes: 0.5*(a+b+c) - 0.5*(a*b*c)
__device__ __forceinline__ ull maj3p(ull a, ull b, ull c, ull h2, ull nh2) {
    ull s = addp(addp(a, b), c);
    ull q = mulp(mulp(a, b), c);
    return fmap(q, nh2, mulp(s, h2));
}

// grid (HH, OC/4, NB), 128 threads.
// thread -> pixel pair p = tid&31 (cols 2p, 2p+1), oc_local = tid>>5 (0..3).
__global__ __launch_bounds__(128, 7) void sconv_kernel(const float* __restrict__ x,
                                                       const float* __restrict__ wraw,
                                                       float* __restrict__ out) {
    __shared__ __align__(16) float  tile[81 * PITCH];   // [row=c*3+r][col 0..65], col0/col65 = zero halo
    __shared__ __align__(16) float2 wdup[4 * 81 * 4];   // [ol*81+win][4]: (w0/2)x2,(w1/2)x2,(w2/2)x2,(-w0w1w2/2)x2

    const int h   = blockIdx.x;
    const int ocg = blockIdx.y;
    const int n   = blockIdx.z;
    const int tid = threadIdx.x;

    // pack+duplicate weights for the block's 4 ocs (same loop structure as the passing kernel)
    for (int i = tid; i < 4 * 81; i += 128) {
        int ol2 = i / 81;
        int win = i - ol2 * 81;
        const float* pw = wraw + (ocg * 4 + ol2) * 243 + win * 3;
        float a = pw[0], b = pw[1], c = pw[2];
        float2* d = &wdup[i * 4];
        d[0] = make_float2(0.5f * a, 0.5f * a);
        d[1] = make_float2(0.5f * b, 0.5f * b);
        d[2] = make_float2(0.5f * c, 0.5f * c);
        float t = -0.5f * a * b * c;
        d[3] = make_float2(t, t);
    }

    // halo columns (gw=-1, gw=64) are always outside the image -> zero
    for (int i = tid; i < 162; i += 128) {
        int row = i >> 1;
        tile[row * PITCH + ((i & 1) ? 65 : 0)] = 0.0f;
    }

    // interior: 81 rows x 64 cols
    {
        const float* xb = x + (size_t)n * NCH * HH * WW;
        const int col = tid & 63;
#pragma unroll 4
        for (int row = tid >> 6; row < 81; row += 2) {
            int c  = row / 3;
            int r  = row - 3 * c;
            int gh = h + r - 1;
            float v = 0.0f;
            if ((unsigned)gh < (unsigned)HH)
                v = xb[c * (HH * WW) + gh * WW + col];
            tile[row * PITCH + 1 + col] = v;
        }
    }
    __syncthreads();

    const int p  = tid & 31;   // pixel pair: output cols 2p, 2p+1
    const int ol = tid >> 5;   // oc within group (uniform per warp -> broadcast weight LDS)
    const float2* t2 = reinterpret_cast<const float2*>(tile);
    const ulonglong2* wp =
        reinterpret_cast<const ulonglong2*>(wdup + (size_t)ol * 81 * 4);

    const ull h2  = pack2(0.5f, 0.5f);
    const ull nh2 = pack2(-0.5f, -0.5f);

    ull a3[3];
#pragma unroll
    for (int g3 = 0; g3 < 3; g3++) {
        ull a9[3];
#pragma unroll
        for (int g9 = 0; g9 < 3; g9++) {
            ull ch[3];
#pragma unroll
            for (int cc = 0; cc < 3; cc++) {
                const int c = g3 * 9 + g9 * 3 + cc;
                ull rr[3];
#pragma unroll
                for (int ki = 0; ki < 3; ki++) {
                    const int row = c * 3 + ki;
                    float2 u = t2[row * (PITCH / 2) + p];       // t0, t1
                    float2 v = t2[row * (PITCH / 2) + p + 1];   // t2, t3

                    ull X0 = pack2(u.x, u.y);   // lanes: (t0 | t1)
                    ull X1 = pack2(u.y, v.x);   //        (t1 | t2)
                    ull X2 = pack2(v.x, v.y);   //        (t2 | t3)

                    ulonglong2 W01 = wp[row * 2 + 0];   // (w0/2)x2, (w1/2)x2
                    ulonglong2 W23 = wp[row * 2 + 1];   // (w2/2)x2, (-w0w1w2/2)x2

                    ull s = mulp(X0, W01.x);
                    s = fmap(X1, W01.y, s);
                    s = fmap(X2, W23.x, s);
                    ull P = mulp(mulp(X0, X1), X2);     // (t0t1t2 | t1t2t3)
                    rr[ki] = fmap(P, W23.y, s);         // folded leaf maj3
                }
                ch[cc] = maj3p(rr[0], rr[1], rr[2], h2, nh2);
            }
            a9[g9] = maj3p(ch[0], ch[1], ch[2], h2, nh2);
        }
        a3[g3] = maj3p(a9[0], a9[1], a9[2], h2, nh2);
    }
    ull res = maj3p(a3[0], a3[1], a3[2], h2, nh2);

    const int oc = ocg * 4 + ol;
    ull* op = reinterpret_cast<ull*>(out + (((size_t)n * OC + oc) * HH + h) * WW);
    op[p] = res;
}

extern "C" void kernel_launch(void* const* d_in, const int* in_sizes, int n_in,
                              void* d_out, int out_size) {
    const float* x = (const float*)d_in[0];
    const float* w = (const float*)d_in[1];
    float* out = (float*)d_out;

    dim3 grid(HH, OC / 4, NB);
    sconv_kernel<<<grid, 128>>>(x, w, out);
}

// round 12
// speedup vs baseline: 1.0952x; 1.0952x over previous
#include <cuda_runtime.h>

#define NCH 27
#define HH 64
#define WW 64
#define OC 32
#define NB 2
#define PITCH 68            // floats per tile row; keeps ull loads 8B-aligned
#define PITCH8 34           // ull per tile row

typedef unsigned long long ull;

__device__ __forceinline__ ull addp(ull a, ull b) {
    ull r; asm("add.rn.f32x2 %0, %1, %2;" : "=l"(r) : "l"(a), "l"(b)); return r;
}
__device__ __forceinline__ ull mulp(ull a, ull b) {
    ull r; asm("mul.rn.f32x2 %0, %1, %2;" : "=l"(r) : "l"(a), "l"(b)); return r;
}
__device__ __forceinline__ ull fmap(ull a, ull b, ull c) {
    ull r; asm("fma.rn.f32x2 %0, %1, %2, %3;" : "=l"(r) : "l"(a), "l"(b), "l"(c)); return r;
}
__device__ __forceinline__ ull pack2u(unsigned lo, unsigned hi) {
    ull r; asm("mov.b64 %0, {%1, %2};" : "=l"(r) : "r"(lo), "r"(hi)); return r;
}
__device__ __forceinline__ ull pack2(float lo, float hi) {
    return pack2u(__float_as_uint(lo), __float_as_uint(hi));
}
__device__ __forceinline__ void unpack2(ull v, unsigned& lo, unsigned& hi) {
    asm("mov.b64 {%0, %1}, %2;" : "=r"(lo), "=r"(hi) : "l"(v));
}

// packed maj3 on both lanes: 0.5*(a+b+c) - 0.5*(a*b*c)
__device__ __forceinline__ ull maj3p(ull a, ull b, ull c, ull h2, ull nh2) {
    ull s = addp(addp(a, b), c);
    ull q = mulp(mulp(a, b), c);
    return fmap(q, nh2, mulp(s, h2));
}

// grid (HH, OC/4, NB), 128 threads = 32 pixel-pairs x 4 ocs.
// Each thread computes pixels (2p, 2p+1) for one oc, both lanes packed f32x2.
// Channels processed in 3 phases of 9 (small smem -> occupancy at grid cap).
// NOTE: resubmission of the R10 kernel — previous bench died on a transient
// "device busy" broker error before launch; no kernel signal was obtained.
__global__ __launch_bounds__(128, 7) void sconv_kernel(const float* __restrict__ x,
                                                       const float* __restrict__ wraw,
                                                       float* __restrict__ out) {
    __shared__ __align__(16) float  tile[27 * PITCH];   // 9 channels x 3 rows; col0/col65 = zero halo
    __shared__ __align__(16) float2 wdup[4 * 27 * 4];   // [ol][win 0..26][4]: dup (w0/2),(w1/2),(w2/2),(-w0w1w2/2)

    const int h   = blockIdx.x;
    const int ocg = blockIdx.y;
    const int n   = blockIdx.z;
    const int tid = threadIdx.x;

    const int p  = tid & 31;   // pixel pair: output cols 2p, 2p+1
    const int ol = tid >> 5;   // oc within group (uniform per warp -> broadcast weight LDS)

    const ull h2  = pack2(0.5f, 0.5f);
    const ull nh2 = pack2(-0.5f, -0.5f);

    // halo columns (gw=-1, gw=64) always outside image -> zero; never overwritten
    for (int i = tid; i < 54; i += 128) {
        int row = i >> 1;
        tile[row * PITCH + ((i & 1) ? 65 : 0)] = 0.0f;
    }

    const float* xb = x + (size_t)n * NCH * HH * WW;
    const ull*   t8 = reinterpret_cast<const ull*>(tile);
    const ulonglong2* wp = reinterpret_cast<const ulonglong2*>(wdup) + ol * 54;

    ull a3[3];

    for (int g3 = 0; g3 < 3; g3++) {
        __syncthreads();   // prior-phase consumers done (and halo writes on first pass)

        // x tile: channels 9*g3 .. 9*g3+8, 3 rows each, 64 interior cols
        for (int idx = tid; idx < 27 * 64; idx += 128) {
            int row = idx >> 6;          // 0..26 = cp*3 + r
            int col = idx & 63;
            int cp  = row / 3;
            int r   = row - 3 * cp;
            int gh  = h + r - 1;
            float v = 0.0f;
            if ((unsigned)gh < (unsigned)HH)
                v = xb[(9 * g3 + cp) * (HH * WW) + gh * WW + col];
            tile[row * PITCH + 1 + col] = v;
        }

        // duplicated half-weights for this phase: win = cp*3+ki (0..26)
        for (int i = tid; i < 4 * 27; i += 128) {
            int o   = i / 27;
            int win = i - o * 27;
            const float* pw = wraw + (ocg * 4 + o) * 243 + 81 * g3 + win * 3;
            float a = pw[0], b = pw[1], c = pw[2];
            float2* d = &wdup[i * 4];
            d[0] = make_float2(0.5f * a, 0.5f * a);
            d[1] = make_float2(0.5f * b, 0.5f * b);
            d[2] = make_float2(0.5f * c, 0.5f * c);
            float t = -0.5f * a * b * c;
            d[3] = make_float2(t, t);
        }
        __syncthreads();

        ull a9[3];
#pragma unroll
        for (int g9 = 0; g9 < 3; g9++) {
            ull ch[3];
#pragma unroll
            for (int cc = 0; cc < 3; cc++) {
                const int cp = g9 * 3 + cc;    // channel within phase
                ull rr[3];
#pragma unroll
                for (int ki = 0; ki < 3; ki++) {
                    const int row = cp * 3 + ki;
                    ull X0 = t8[row * PITCH8 + p];       // (t0 | t1), low word = lane 0
                    ull X2 = t8[row * PITCH8 + p + 1];   // (t2 | t3)
                    unsigned l0, h0, l2, h2b;
                    unpack2(X0, l0, h0);
                    unpack2(X2, l2, h2b);
                    (void)l0; (void)h2b;
                    ull X1 = pack2u(h0, l2);             // (t1 | t2)

                    ulonglong2 W01 = wp[row * 2 + 0];    // (w0/2)x2, (w1/2)x2
                    ulonglong2 W23 = wp[row * 2 + 1];    // (w2/2)x2, (-w0w1w2/2)x2

                    ull s = mulp(X0, W01.x);
                    s = fmap(X1, W01.y, s);
                    s = fmap(X2, W23.x, s);
                    ull P = mulp(mulp(X0, X1), X2);      // (t0t1t2 | t1t2t3)
                    rr[ki] = fmap(P, W23.y, s);          // folded leaf maj3
                }
                ch[cc] = maj3p(rr[0], rr[1], rr[2], h2, nh2);
            }
            a9[g9] = maj3p(ch[0], ch[1], ch[2], h2, nh2);
        }
        a3[g3] = maj3p(a9[0], a9[1], a9[2], h2, nh2);
    }

    ull res = maj3p(a3[0], a3[1], a3[2], h2, nh2);

    const int oc = ocg * 4 + ol;
    ull* op = reinterpret_cast<ull*>(out + (((size_t)n * OC + oc) * HH + h) * WW);
    op[p] = res;
}

extern "C" void kernel_launch(void* const* d_in, const int* in_sizes, int n_in,
                              void* d_out, int out_size) {
    const float* x = (const float*)d_in[0];
    const float* w = (const float*)d_in[1];
    float* out = (float*)d_out;

    dim3 grid(HH, OC / 4, NB);
    sconv_kernel<<<grid, 128>>>(x, w, out);
}